// round 9
// baseline (speedup 1.0000x reference)
#include <cuda_runtime.h>
#include <cstdint>

#define NT1      256
#define MTILE    128
#define NH       64
#define NB       64
#define DIMC     1024

// epilogue overlay smem
#define OFF_ZS   0              // float[128*66] = 33792 B
#define OFF_OWT  33792          // float[64*64]  = 16384 B
#define OFF_P1   50176
#define OFF_P2   51200
#define SMEM_TOTAL 52224

__device__ float4 g_q[NH * NB];
__device__ float  g_owt[NH * NB];          // out_weight transposed [k][h]
__device__ float4 g_p1[NH];                // {c0', sq, d, A}
__device__ float4 g_p2[NH];                // {B, 2B, 2^{2B}, 0}
__device__ int    g_bad = 0;
// B fragments in MMA order: [ks 0..63][nt8 0..7][lane 0..31] x uint4{bh0,bh1,bl0,bl1}
__device__ __align__(16) unsigned char g_bf[64 * 8 * 512];

static __device__ __forceinline__ uint32_t smem_u32(const void* p) {
    uint32_t a;
    asm("{ .reg .u64 t; cvta.to.shared.u64 t, %1; cvt.u32.u64 %0, t; }" : "=r"(a) : "l"(p));
    return a;
}

#define FMA2(acc, a, b) asm("fma.rn.f32x2 %0, %1, %2, %0;" : "+l"(acc) : "l"(a), "l"(b))
#define MUL2(d, a, b)   asm("mul.rn.f32x2 %0, %1, %2;" : "=l"(d) : "l"(a), "l"(b))
#define PACK2(d, lo, hi) asm("mov.b64 %0, {%1, %2};" : "=l"(d) : "f"(lo), "f"(hi))

#define MMA(c, a0, a1, a2, a3, b0, b1) \
    asm volatile("mma.sync.aligned.m16n8k16.row.col.f32.bf16.bf16.f32 " \
                 "{%0,%1,%2,%3}, {%4,%5,%6,%7}, {%8,%9}, {%0,%1,%2,%3};" \
                 : "+f"((c)[0]), "+f"((c)[1]), "+f"((c)[2]), "+f"((c)[3]) \
                 : "r"(a0), "r"(a1), "r"(a2), "r"(a3), "r"(b0), "r"(b1))

// fp32 pair -> bf16x2 hi (truncation) + bf16x2 lo (residual)
static __device__ __forceinline__ void cvt_pair(float2 f, uint32_t& hi, uint32_t& lo) {
    uint32_t u0 = __float_as_uint(f.x), u1 = __float_as_uint(f.y);
    hi = __byte_perm(u0, u1, 0x7632);
    float l0 = f.x - __uint_as_float(u0 & 0xffff0000u);
    float l1 = f.y - __uint_as_float(u1 & 0xffff0000u);
    asm("cvt.rn.bf16x2.f32 %0, %1, %2;" : "=r"(lo) : "f"(l1), "f"(l0));
}

// ---- prep: blocks 0-63 build B fragment table; blocks 64-79 coeff tables ----
__global__ void rbf_prep(const float* __restrict__ in_b,
                         const float* __restrict__ centers,
                         const float* __restrict__ log_widths,
                         const float* __restrict__ out_weight,
                         const float* __restrict__ in_w)
{
    const int bid = blockIdx.x;
    const int tid = threadIdx.x;

    if (bid < 64) {
        int t = bid * 256 + tid;          // 0..16383
        int ks   = t >> 8;                // k16 step
        int nt8  = (t >> 5) & 7;          // n-tile of 8 h
        int lane = t & 31;
        int n  = nt8 * 8 + (lane >> 2);
        int kk = ks * 16 + 2 * (lane & 3);
        const float* wr = in_w + n * DIMC + kk;
        float2 wa = make_float2(wr[0], wr[1]);
        float2 wb = make_float2(wr[8], wr[9]);
        uint32_t bh0, bl0, bh1, bl1;
        cvt_pair(wa, bh0, bl0);
        cvt_pair(wb, bh1, bl1);
        *(uint4*)(g_bf + (size_t)(ks * 8 + nt8) * 512 + lane * 16) =
            make_uint4(bh0, bh1, bl0, bl1);
        return;
    }

    const int i = (bid - 64) * 256 + tid;   // 0..4095
    const int h = i >> 6;
    const int k = i & 63;

    float lw = log_widths[i];
    float sp = (lw > 15.f) ? lw : log1pf(expf(lw));
    float w = sp + 0.001f;
    float s = -1.4426950408889634f / (w * w);
    float c = centers[i] - in_b[h];
    float4 q;
    q.x = s; q.y = -2.f * s * c; q.z = s * c * c; q.w = out_weight[i];
    g_q[i] = q;
    g_owt[i] = out_weight[((i & 63) << 6) + (i >> 6)];

    float c0  = centers[h * NB];
    float d   = (centers[h * NB + NB - 1] - c0) / (float)(NB - 1);
    float lw0 = log_widths[h * NB];
    bool ok = (fabsf(centers[i] - fmaf((float)k, d, c0)) <= 1e-5f) &&
              (fabsf(lw - lw0) <= 1e-6f);
    if (!ok) atomicAdd(&g_bad, 1);

    if (k == 0) {
        float sp0 = (lw0 > 15.f) ? lw0 : log1pf(expf(lw0));
        float w0  = sp0 + 0.001f;
        float sq  = -1.4426950408889634f / (w0 * w0);
        float A   = -2.f * sq * d;
        float B   = sq * d * d;
        float4 p1, p2;
        p1.x = c0 - in_b[h]; p1.y = sq; p1.z = d; p1.w = A;
        p2.x = B; p2.y = 2.f * B; p2.z = exp2f(2.f * B); p2.w = 0.f;
        g_p1[h] = p1; g_p2[h] = p2;
    }
}

// ---- fused GEMM + RBF: no smem / no syncs in mainloop ----
__global__ void __launch_bounds__(NT1, 3)
rbf_fused_kernel(const float* __restrict__ x,
                 const float* __restrict__ out_bias,
                 float* __restrict__ out)
{
    extern __shared__ char smem[];
    const uint32_t sb = smem_u32(smem);
    const int tid = threadIdx.x;
    const int wid = tid >> 5;
    const int l   = tid & 31;
    const int wq  = wid & 3;              // token quarter (32 tok)
    const int wh  = wid >> 2;             // h half (32 h)
    const int tok0 = blockIdx.x * MTILE;

    float acc[2][4][4];
#pragma unroll
    for (int m = 0; m < 2; ++m)
#pragma unroll
        for (int nt = 0; nt < 4; ++nt)
#pragma unroll
            for (int j = 0; j < 4; ++j) acc[m][nt][j] = 0.f;

    // A fragment base: row = tok0 + wq*32 + l/4, col = 2*(l%4)
    const char* ap = (const char*)(x + (size_t)(tok0 + wq * 32 + (l >> 2)) * DIMC
                                     + 2 * (l & 3));
    const char* bp = (const char*)g_bf + (size_t)(wh * 4) * 512 + (size_t)l * 16;

#pragma unroll 2
    for (int ks = 0; ks < 64; ++ks) {
        uint32_t ah[2][4], al[2][4];
#pragma unroll
        for (int m = 0; m < 2; ++m) {
            const char* am = ap + m * 65536;            // +16 rows
            float2 f0 = __ldg((const float2*)(am));
            float2 f1 = __ldg((const float2*)(am + 32768));   // +8 rows
            float2 f2 = __ldg((const float2*)(am + 32));      // +8 cols
            float2 f3 = __ldg((const float2*)(am + 32800));
            cvt_pair(f0, ah[m][0], al[m][0]);
            cvt_pair(f1, ah[m][1], al[m][1]);
            cvt_pair(f2, ah[m][2], al[m][2]);
            cvt_pair(f3, ah[m][3], al[m][3]);
        }
#pragma unroll
        for (int nt = 0; nt < 4; ++nt) {
            uint4 b = __ldg((const uint4*)(bp + nt * 512));
#pragma unroll
            for (int m = 0; m < 2; ++m) {
                MMA(acc[m][nt], ah[m][0], ah[m][1], ah[m][2], ah[m][3], b.x, b.y);
                MMA(acc[m][nt], ah[m][0], ah[m][1], ah[m][2], ah[m][3], b.z, b.w);
                MMA(acc[m][nt], al[m][0], al[m][1], al[m][2], al[m][3], b.x, b.y);
            }
        }
        ap += 64;        // 16 k-floats
        bp += 4096;      // next ks row of frag table
    }

    // ---- overlay: z -> smem [128][66], stage tables ----
    {
        float* zs = (float*)(smem + OFF_ZS);
        const int g = l >> 2, t = l & 3;
#pragma unroll
        for (int m = 0; m < 2; ++m)
#pragma unroll
            for (int nt = 0; nt < 4; ++nt) {
                int tok = wq * 32 + m * 16 + g;
                int hcol = wh * 32 + nt * 8 + 2 * t;
                *(float2*)(zs + tok * 66 + hcol)       = make_float2(acc[m][nt][0], acc[m][nt][1]);
                *(float2*)(zs + (tok + 8) * 66 + hcol) = make_float2(acc[m][nt][2], acc[m][nt][3]);
            }
        float4* owt = (float4*)(smem + OFF_OWT);
        const float4* gow = (const float4*)g_owt;
#pragma unroll
        for (int j = 0; j < 4; ++j) owt[j * NT1 + tid] = gow[j * NT1 + tid];
        if (tid < NH) {
            ((float4*)(smem + OFF_P1))[tid] = g_p1[tid];
            ((float4*)(smem + OFF_P2))[tid] = g_p2[tid];
        }
    }
    __syncthreads();

    // ---- epilogue: thread = 4 tokens x 8 h ----
    const int hq = tid & 7;
    const int p  = tid >> 3;
    const float* zs = (const float*)(smem + OFF_ZS);
    const float4* p1s = (const float4*)(smem + OFF_P1);
    const float4* p2s = (const float4*)(smem + OFF_P2);
    float sum[4];

    if (g_bad == 0) {
        unsigned long long acc2[4] = {0ull, 0ull, 0ull, 0ull};
#pragma unroll
        for (int hp = 0; hp < 4; ++hp) {
            const int h0 = hq * 8 + 2 * hp;
            float4 Pa = p1s[h0], Pb = p1s[h0 + 1];
            float4 Qa = p2s[h0], Qb = p2s[h0 + 1];
            unsigned long long tt;
            PACK2(tt, Qa.z, Qb.z);
            float u0[4], u1[4], rb0[4], rb1[4];
#pragma unroll
            for (int j = 0; j < 4; ++j) {
                float2 zz = *(const float2*)(zs + (p + 32 * j) * 66 + h0);
                u0[j] = zz.x - Pa.x;  u1[j] = zz.y - Pb.x;
                rb0[j] = fmaf(Pa.w, u0[j], Qa.x);
                rb1[j] = fmaf(Pb.w, u1[j], Qb.x);
            }
            const uint32_t owbase = sb + OFF_OWT + (uint32_t)h0 * 4u;
#pragma unroll
            for (int m = 0; m < 4; ++m) {
                const float km = (float)(16 * m);
                unsigned long long e[4], r[4];
#pragma unroll
                for (int j = 0; j < 4; ++j) {
                    float v0 = fmaf(-km, Pa.z, u0[j]);
                    float v1 = fmaf(-km, Pb.z, u1[j]);
                    float e0, e1, rr0, rr1;
                    float a0 = Pa.y * v0 * v0, a1 = Pb.y * v1 * v1;
                    asm("ex2.approx.f32 %0, %1;" : "=f"(e0) : "f"(a0));
                    asm("ex2.approx.f32 %0, %1;" : "=f"(e1) : "f"(a1));
                    float b0 = fmaf(km, Qa.y, rb0[j]), b1 = fmaf(km, Qb.y, rb1[j]);
                    asm("ex2.approx.f32 %0, %1;" : "=f"(rr0) : "f"(b0));
                    asm("ex2.approx.f32 %0, %1;" : "=f"(rr1) : "f"(b1));
                    PACK2(e[j], e0, e1);
                    PACK2(r[j], rr0, rr1);
                }
                uint32_t a = owbase + (uint32_t)m * (16u * 256u);
#pragma unroll
                for (int kk = 0; kk < 16; ++kk) {
                    unsigned long long w2;
                    asm volatile("ld.shared.b64 %0, [%1];" : "=l"(w2) : "r"(a));
                    a += 256u;
#pragma unroll
                    for (int j = 0; j < 4; ++j) {
                        FMA2(acc2[j], e[j], w2);
                        MUL2(e[j], e[j], r[j]);
                        MUL2(r[j], r[j], tt);
                    }
                }
            }
        }
#pragma unroll
        for (int j = 0; j < 4; ++j) {
            float lo, hi;
            asm("mov.b64 {%0,%1}, %2;" : "=f"(lo), "=f"(hi) : "l"(acc2[j]));
            sum[j] = lo + hi;
        }
    } else {
#pragma unroll
        for (int j = 0; j < 4; ++j) sum[j] = 0.f;
#pragma unroll 1
        for (int i = 0; i < 8; ++i) {
            const int h = hq * 8 + i;
            const float4* qh = g_q + h * NB;
            float zh[4];
#pragma unroll
            for (int j = 0; j < 4; ++j) zh[j] = zs[(p + 32 * j) * 66 + h];
#pragma unroll 8
            for (int k = 0; k < NB; ++k) {
                float4 q = qh[k];
#pragma unroll
                for (int j = 0; j < 4; ++j) {
                    float pp = fmaf(fmaf(q.x, zh[j], q.y), zh[j], q.z);
                    float e;
                    asm("ex2.approx.f32 %0, %1;" : "=f"(e) : "f"(pp));
                    sum[j] = fmaf(e, q.w, sum[j]);
                }
            }
        }
    }

    const float ob = __ldg(out_bias);
#pragma unroll
    for (int j = 0; j < 4; ++j) {
        float v = sum[j];
        v += __shfl_xor_sync(0xffffffffu, v, 1);
        v += __shfl_xor_sync(0xffffffffu, v, 2);
        v += __shfl_xor_sync(0xffffffffu, v, 4);
        if (hq == 0) out[tok0 + p + 32 * j] = v + ob;
    }
}

extern "C" void kernel_launch(void* const* d_in, const int* in_sizes, int n_in,
                              void* d_out, int out_size)
{
    const float* x          = (const float*)d_in[0];
    const float* in_w       = (const float*)d_in[1];
    const float* in_b       = (const float*)d_in[2];
    const float* centers    = (const float*)d_in[3];
    const float* log_widths = (const float*)d_in[4];
    const float* out_weight = (const float*)d_in[5];
    const float* out_bias   = (const float*)d_in[6];
    float* out = (float*)d_out;

    int ntok = in_sizes[0] / DIMC;          // 65536

    rbf_prep<<<80, 256>>>(in_b, centers, log_widths, out_weight, in_w);

    cudaFuncSetAttribute(rbf_fused_kernel,
                         cudaFuncAttributeMaxDynamicSharedMemorySize, SMEM_TOTAL);
    rbf_fused_kernel<<<ntok / MTILE, NT1, SMEM_TOTAL>>>(x, out_bias, out);
}

// round 10
// speedup vs baseline: 1.1981x; 1.1981x over previous
#include <cuda_runtime.h>
#include <cstdint>

#define NT1      256
#define MTILE    128
#define NH       64
#define NB       64
#define DIMC     1024

// pipeline stages: A fp32 slice (8 KB, swizzled) + B frag slice (4 KB)
#define STAGE    12288
#define BOFF     8192
// epilogue overlay smem
#define OFF_ZS   0              // float[128*66] = 33792 B
#define OFF_OWT  33792          // float[64*64]  = 16384 B
#define OFF_P1   50176
#define OFF_P2   51200
#define SMEM_TOTAL 52224        // > 4*STAGE = 49152

__device__ float4 g_q[NH * NB];
__device__ float  g_owt[NH * NB];          // out_weight transposed [k][h]
__device__ float4 g_p1[NH];                // {c0', sq, d, A}
__device__ float4 g_p2[NH];                // {B, 2B, 2^{2B}, 0}
__device__ int    g_bad = 0;
// B fragments in MMA order: [ks 0..63][nt8 0..7][lane 0..31] x uint4{bh0,bh1,bl0,bl1}
__device__ __align__(16) unsigned char g_bf[64 * 8 * 512];

static __device__ __forceinline__ uint32_t smem_u32(const void* p) {
    uint32_t a;
    asm("{ .reg .u64 t; cvta.to.shared.u64 t, %1; cvt.u32.u64 %0, t; }" : "=r"(a) : "l"(p));
    return a;
}

#define FMA2(acc, a, b) asm("fma.rn.f32x2 %0, %1, %2, %0;" : "+l"(acc) : "l"(a), "l"(b))
#define MUL2(d, a, b)   asm("mul.rn.f32x2 %0, %1, %2;" : "=l"(d) : "l"(a), "l"(b))
#define PACK2(d, lo, hi) asm("mov.b64 %0, {%1, %2};" : "=l"(d) : "f"(lo), "f"(hi))

#define CP_ASYNC16(dst, src) \
    asm volatile("cp.async.ca.shared.global [%0], [%1], 16;" :: "r"(dst), "l"(src) : "memory")
#define CP_COMMIT() asm volatile("cp.async.commit_group;" ::: "memory")
#define CP_WAIT2()  asm volatile("cp.async.wait_group 2;" ::: "memory")

#define LDS64F(f, a) \
    asm volatile("ld.shared.v2.f32 {%0,%1}, [%2];" : "=f"((f).x), "=f"((f).y) : "r"(a))
#define LDS128U(u, a) \
    asm volatile("ld.shared.v4.b32 {%0,%1,%2,%3}, [%4];" \
                 : "=r"((u).x), "=r"((u).y), "=r"((u).z), "=r"((u).w) : "r"(a))

#define MMA(c, a0, a1, a2, a3, b0, b1) \
    asm volatile("mma.sync.aligned.m16n8k16.row.col.f32.bf16.bf16.f32 " \
                 "{%0,%1,%2,%3}, {%4,%5,%6,%7}, {%8,%9}, {%0,%1,%2,%3};" \
                 : "+f"((c)[0]), "+f"((c)[1]), "+f"((c)[2]), "+f"((c)[3]) \
                 : "r"(a0), "r"(a1), "r"(a2), "r"(a3), "r"(b0), "r"(b1))

// fp32 pair -> bf16x2 hi (truncation) + bf16x2 lo (residual)
static __device__ __forceinline__ void cvt_pair(float2 f, uint32_t& hi, uint32_t& lo) {
    uint32_t u0 = __float_as_uint(f.x), u1 = __float_as_uint(f.y);
    hi = __byte_perm(u0, u1, 0x7632);
    float l0 = f.x - __uint_as_float(u0 & 0xffff0000u);
    float l1 = f.y - __uint_as_float(u1 & 0xffff0000u);
    asm("cvt.rn.bf16x2.f32 %0, %1, %2;" : "=r"(lo) : "f"(l1), "f"(l0));
}

// ---- prep: blocks 0-63 build B fragment table; blocks 64-79 coeff tables ----
__global__ void rbf_prep(const float* __restrict__ in_b,
                         const float* __restrict__ centers,
                         const float* __restrict__ log_widths,
                         const float* __restrict__ out_weight,
                         const float* __restrict__ in_w)
{
    const int bid = blockIdx.x;
    const int tid = threadIdx.x;

    if (bid < 64) {
        int t = bid * 256 + tid;          // 0..16383
        int ks   = t >> 8;
        int nt8  = (t >> 5) & 7;
        int lane = t & 31;
        int n  = nt8 * 8 + (lane >> 2);
        int kk = ks * 16 + 2 * (lane & 3);
        const float* wr = in_w + n * DIMC + kk;
        float2 wa = make_float2(wr[0], wr[1]);
        float2 wb = make_float2(wr[8], wr[9]);
        uint32_t bh0, bl0, bh1, bl1;
        cvt_pair(wa, bh0, bl0);
        cvt_pair(wb, bh1, bl1);
        *(uint4*)(g_bf + (size_t)(ks * 8 + nt8) * 512 + lane * 16) =
            make_uint4(bh0, bh1, bl0, bl1);
        return;
    }

    const int i = (bid - 64) * 256 + tid;   // 0..4095
    const int h = i >> 6;
    const int k = i & 63;

    float lw = log_widths[i];
    float sp = (lw > 15.f) ? lw : log1pf(expf(lw));
    float w = sp + 0.001f;
    float s = -1.4426950408889634f / (w * w);
    float c = centers[i] - in_b[h];
    float4 q;
    q.x = s; q.y = -2.f * s * c; q.z = s * c * c; q.w = out_weight[i];
    g_q[i] = q;
    g_owt[i] = out_weight[((i & 63) << 6) + (i >> 6)];

    float c0  = centers[h * NB];
    float d   = (centers[h * NB + NB - 1] - c0) / (float)(NB - 1);
    float lw0 = log_widths[h * NB];
    bool ok = (fabsf(centers[i] - fmaf((float)k, d, c0)) <= 1e-5f) &&
              (fabsf(lw - lw0) <= 1e-6f);
    if (!ok) atomicAdd(&g_bad, 1);

    if (k == 0) {
        float sp0 = (lw0 > 15.f) ? lw0 : log1pf(expf(lw0));
        float w0  = sp0 + 0.001f;
        float sq  = -1.4426950408889634f / (w0 * w0);
        float A   = -2.f * sq * d;
        float B   = sq * d * d;
        float4 p1, p2;
        p1.x = c0 - in_b[h]; p1.y = sq; p1.z = d; p1.w = A;
        p2.x = B; p2.y = 2.f * B; p2.z = exp2f(2.f * B); p2.w = 0.f;
        g_p1[h] = p1; g_p2[h] = p2;
    }
}

// ---- fused GEMM + RBF: cp.async 4-stage pipeline, direct fragment LDS ----
__global__ void __launch_bounds__(NT1, 3)
rbf_fused_kernel(const float* __restrict__ x,
                 const float* __restrict__ out_bias,
                 float* __restrict__ out)
{
    extern __shared__ char smem[];
    const uint32_t sb = smem_u32(smem);
    const int tid = threadIdx.x;
    const int wid = tid >> 5;
    const int l   = tid & 31;
    const int wq  = wid & 3;              // token quarter (32 tok)
    const int wh  = wid >> 2;             // h half (32 h)
    const int tok0 = blockIdx.x * MTILE;

    float acc[2][4][4];
#pragma unroll
    for (int m = 0; m < 2; ++m)
#pragma unroll
        for (int nt = 0; nt < 4; ++nt)
#pragma unroll
            for (int j = 0; j < 4; ++j) acc[m][nt][j] = 0.f;

    // --- cp.async producer constants ---
    const int arow  = tid >> 1;            // 0..127 token row
    const int ahalf = tid & 1;             // 32B half of the 64B row slice
    const float* asrc = x + (size_t)(tok0 + arow) * DIMC + ahalf * 8;
    const uint32_t adst = (uint32_t)(arow * 64 + ((ahalf * 32) ^ ((arow & 2) << 4)));
    const char* bsrc = (const char*)g_bf + (size_t)tid * 16;
    const uint32_t bdst = BOFF + (uint32_t)tid * 16;

    // --- consumer constants ---
    const int rA = wq * 32 + (l >> 2);
    const uint32_t xa  = (uint32_t)((rA & 2) << 4);
    const uint32_t ca0 = ((uint32_t)(8 * (l & 3))) ^ xa;
    const uint32_t ca1 = ((uint32_t)(8 * (l & 3) + 32)) ^ xa;
    const uint32_t aoff = (uint32_t)rA * 64u;
    const uint32_t boff = BOFF + (uint32_t)(wh * 4) * 512u + (uint32_t)l * 16u;

    // prologue: stages 0..2
#pragma unroll
    for (int s = 0; s < 3; ++s) {
        const uint32_t bufo = sb + (uint32_t)s * STAGE;
        CP_ASYNC16(bufo + adst, asrc + s * 16);
        CP_ASYNC16(bufo + adst + 16, asrc + s * 16 + 4);
        CP_ASYNC16(bufo + bdst, bsrc + (size_t)s * 4096);
        CP_COMMIT();
    }

#pragma unroll 1
    for (int kb = 0; kb < 16; ++kb) {
#pragma unroll
        for (int j = 0; j < 4; ++j) {
            const int ks = kb * 4 + j;
            CP_WAIT2();
            __syncthreads();
            if (ks + 3 < 64) {
                const uint32_t bufo = sb + (uint32_t)((j + 3) & 3) * STAGE;
                CP_ASYNC16(bufo + adst, asrc + (ks + 3) * 16);
                CP_ASYNC16(bufo + adst + 16, asrc + (ks + 3) * 16 + 4);
                CP_ASYNC16(bufo + bdst, bsrc + (size_t)(ks + 3) * 4096);
            }
            CP_COMMIT();

            const uint32_t ab = sb + (uint32_t)j * STAGE;
            uint32_t ah[2][4], al[2][4];
#pragma unroll
            for (int m = 0; m < 2; ++m) {
                const uint32_t ra = ab + aoff + (uint32_t)m * 1024u;
                float2 f0, f1, f2, f3;
                LDS64F(f0, ra + ca0);
                LDS64F(f1, ra + 512u + ca0);
                LDS64F(f2, ra + ca1);
                LDS64F(f3, ra + 512u + ca1);
                cvt_pair(f0, ah[m][0], al[m][0]);
                cvt_pair(f1, ah[m][1], al[m][1]);
                cvt_pair(f2, ah[m][2], al[m][2]);
                cvt_pair(f3, ah[m][3], al[m][3]);
            }
#pragma unroll
            for (int nt = 0; nt < 4; ++nt) {
                uint4 b;
                LDS128U(b, ab + boff + (uint32_t)nt * 512u);
#pragma unroll
                for (int m = 0; m < 2; ++m) {
                    MMA(acc[m][nt], ah[m][0], ah[m][1], ah[m][2], ah[m][3], b.x, b.y);
                    MMA(acc[m][nt], ah[m][0], ah[m][1], ah[m][2], ah[m][3], b.z, b.w);
                    MMA(acc[m][nt], al[m][0], al[m][1], al[m][2], al[m][3], b.x, b.y);
                }
            }
        }
    }
    __syncthreads();

    // ---- overlay: z -> smem [128][66], stage tables ----
    {
        float* zs = (float*)(smem + OFF_ZS);
        const int g = l >> 2, t = l & 3;
#pragma unroll
        for (int m = 0; m < 2; ++m)
#pragma unroll
            for (int nt = 0; nt < 4; ++nt) {
                int tok = wq * 32 + m * 16 + g;
                int hcol = wh * 32 + nt * 8 + 2 * t;
                *(float2*)(zs + tok * 66 + hcol)       = make_float2(acc[m][nt][0], acc[m][nt][1]);
                *(float2*)(zs + (tok + 8) * 66 + hcol) = make_float2(acc[m][nt][2], acc[m][nt][3]);
            }
        float4* owt = (float4*)(smem + OFF_OWT);
        const float4* gow = (const float4*)g_owt;
#pragma unroll
        for (int j = 0; j < 4; ++j) owt[j * NT1 + tid] = gow[j * NT1 + tid];
        if (tid < NH) {
            ((float4*)(smem + OFF_P1))[tid] = g_p1[tid];
            ((float4*)(smem + OFF_P2))[tid] = g_p2[tid];
        }
    }
    __syncthreads();

    // ---- epilogue: thread = 4 tokens x 8 h ----
    const int hq = tid & 7;
    const int p  = tid >> 3;
    const float* zs = (const float*)(smem + OFF_ZS);
    const float4* p1s = (const float4*)(smem + OFF_P1);
    const float4* p2s = (const float4*)(smem + OFF_P2);
    float sum[4];

    if (g_bad == 0) {
        unsigned long long acc2[4] = {0ull, 0ull, 0ull, 0ull};
#pragma unroll
        for (int hp = 0; hp < 4; ++hp) {
            const int h0 = hq * 8 + 2 * hp;
            float4 Pa = p1s[h0], Pb = p1s[h0 + 1];
            float4 Qa = p2s[h0], Qb = p2s[h0 + 1];
            unsigned long long tt;
            PACK2(tt, Qa.z, Qb.z);
            float u0[4], u1[4], rb0[4], rb1[4];
#pragma unroll
            for (int j = 0; j < 4; ++j) {
                float2 zz = *(const float2*)(zs + (p + 32 * j) * 66 + h0);
                u0[j] = zz.x - Pa.x;  u1[j] = zz.y - Pb.x;
                rb0[j] = fmaf(Pa.w, u0[j], Qa.x);
                rb1[j] = fmaf(Pb.w, u1[j], Qb.x);
            }
            const uint32_t owbase = sb + OFF_OWT + (uint32_t)h0 * 4u;
#pragma unroll
            for (int m = 0; m < 4; ++m) {
                const float km = (float)(16 * m);
                unsigned long long e[4], r[4];
#pragma unroll
                for (int j = 0; j < 4; ++j) {
                    float v0 = fmaf(-km, Pa.z, u0[j]);
                    float v1 = fmaf(-km, Pb.z, u1[j]);
                    float e0, e1, rr0, rr1;
                    float a0 = Pa.y * v0 * v0, a1 = Pb.y * v1 * v1;
                    asm("ex2.approx.f32 %0, %1;" : "=f"(e0) : "f"(a0));
                    asm("ex2.approx.f32 %0, %1;" : "=f"(e1) : "f"(a1));
                    float b0 = fmaf(km, Qa.y, rb0[j]), b1 = fmaf(km, Qb.y, rb1[j]);
                    asm("ex2.approx.f32 %0, %1;" : "=f"(rr0) : "f"(b0));
                    asm("ex2.approx.f32 %0, %1;" : "=f"(rr1) : "f"(b1));
                    PACK2(e[j], e0, e1);
                    PACK2(r[j], rr0, rr1);
                }
                uint32_t a = owbase + (uint32_t)m * (16u * 256u);
#pragma unroll
                for (int kk = 0; kk < 16; ++kk) {
                    unsigned long long w2;
                    asm volatile("ld.shared.b64 %0, [%1];" : "=l"(w2) : "r"(a));
                    a += 256u;
#pragma unroll
                    for (int j = 0; j < 4; ++j) {
                        FMA2(acc2[j], e[j], w2);
                        MUL2(e[j], e[j], r[j]);
                        MUL2(r[j], r[j], tt);
                    }
                }
            }
        }
#pragma unroll
        for (int j = 0; j < 4; ++j) {
            float lo, hi;
            asm("mov.b64 {%0,%1}, %2;" : "=f"(lo), "=f"(hi) : "l"(acc2[j]));
            sum[j] = lo + hi;
        }
    } else {
#pragma unroll
        for (int j = 0; j < 4; ++j) sum[j] = 0.f;
#pragma unroll 1
        for (int i = 0; i < 8; ++i) {
            const int h = hq * 8 + i;
            const float4* qh = g_q + h * NB;
            float zh[4];
#pragma unroll
            for (int j = 0; j < 4; ++j) zh[j] = zs[(p + 32 * j) * 66 + h];
#pragma unroll 8
            for (int k = 0; k < NB; ++k) {
                float4 q = qh[k];
#pragma unroll
                for (int j = 0; j < 4; ++j) {
                    float pp = fmaf(fmaf(q.x, zh[j], q.y), zh[j], q.z);
                    float e;
                    asm("ex2.approx.f32 %0, %1;" : "=f"(e) : "f"(pp));
                    sum[j] = fmaf(e, q.w, sum[j]);
                }
            }
        }
    }

    const float ob = __ldg(out_bias);
#pragma unroll
    for (int j = 0; j < 4; ++j) {
        float v = sum[j];
        v += __shfl_xor_sync(0xffffffffu, v, 1);
        v += __shfl_xor_sync(0xffffffffu, v, 2);
        v += __shfl_xor_sync(0xffffffffu, v, 4);
        if (hq == 0) out[tok0 + p + 32 * j] = v + ob;
    }
}

extern "C" void kernel_launch(void* const* d_in, const int* in_sizes, int n_in,
                              void* d_out, int out_size)
{
    const float* x          = (const float*)d_in[0];
    const float* in_w       = (const float*)d_in[1];
    const float* in_b       = (const float*)d_in[2];
    const float* centers    = (const float*)d_in[3];
    const float* log_widths = (const float*)d_in[4];
    const float* out_weight = (const float*)d_in[5];
    const float* out_bias   = (const float*)d_in[6];
    float* out = (float*)d_out;

    int ntok = in_sizes[0] / DIMC;          // 65536

    rbf_prep<<<80, 256>>>(in_b, centers, log_widths, out_weight, in_w);

    cudaFuncSetAttribute(rbf_fused_kernel,
                         cudaFuncAttributeMaxDynamicSharedMemorySize, SMEM_TOTAL);
    rbf_fused_kernel<<<ntok / MTILE, NT1, SMEM_TOTAL>>>(x, out_bias, out);
}

// round 11
// speedup vs baseline: 1.3383x; 1.1170x over previous
#include <cuda_runtime.h>
#include <cstdint>

#define NT1      256
#define MTILE    128
#define NH       64
#define NB       64
#define DIMC     1024

// k32 pipeline stage: A_hi 8K + A_lo 8K + B frags 8K
#define STAGE    24576
#define AHI      0
#define ALO      8192
#define BOFF     16384
// epilogue overlay smem
#define OFF_ZS   0              // float[128*66] = 33792 B
#define OFF_OWT  33792          // float[64*64]  = 16384 B
#define OFF_P1   50176
#define OFF_P2   51200
#define SMEM_TOTAL 52224        // > 2*STAGE = 49152

__device__ float4 g_q[NH * NB];
__device__ float  g_owt[NH * NB];          // out_weight transposed [k][h]
__device__ float4 g_p1[NH];                // {c0', sq, d, A}
__device__ float4 g_p2[NH];                // {B, 2B, 2^{2B}, 0}
__device__ int    g_bad = 0;
// B fragments in MMA order: [ks 0..63][nt8 0..7][lane 0..31] x uint4{bh0,bh1,bl0,bl1}
__device__ __align__(16) unsigned char g_bf[64 * 8 * 512];

static __device__ __forceinline__ uint32_t smem_u32(const void* p) {
    uint32_t a;
    asm("{ .reg .u64 t; cvta.to.shared.u64 t, %1; cvt.u32.u64 %0, t; }" : "=r"(a) : "l"(p));
    return a;
}

#define FMA2(acc, a, b) asm("fma.rn.f32x2 %0, %1, %2, %0;" : "+l"(acc) : "l"(a), "l"(b))
#define MUL2(d, a, b)   asm("mul.rn.f32x2 %0, %1, %2;" : "=l"(d) : "l"(a), "l"(b))
#define PACK2(d, lo, hi) asm("mov.b64 %0, {%1, %2};" : "=l"(d) : "f"(lo), "f"(hi))

#define CP_ASYNC16(dst, src) \
    asm volatile("cp.async.ca.shared.global [%0], [%1], 16;" :: "r"(dst), "l"(src) : "memory")
#define CP_COMMIT() asm volatile("cp.async.commit_group;" ::: "memory")
#define CP_WAIT0()  asm volatile("cp.async.wait_group 0;" ::: "memory")

#define LDSM4(r0, r1, r2, r3, a) \
    asm volatile("ldmatrix.sync.aligned.m8n8.x4.shared.b16 {%0,%1,%2,%3}, [%4];" \
                 : "=r"(r0), "=r"(r1), "=r"(r2), "=r"(r3) : "r"(a))
#define LDS128U(u, a) \
    asm volatile("ld.shared.v4.b32 {%0,%1,%2,%3}, [%4];" \
                 : "=r"((u).x), "=r"((u).y), "=r"((u).z), "=r"((u).w) : "r"(a))

#define MMA(c, a0, a1, a2, a3, b0, b1) \
    asm volatile("mma.sync.aligned.m16n8k16.row.col.f32.bf16.bf16.f32 " \
                 "{%0,%1,%2,%3}, {%4,%5,%6,%7}, {%8,%9}, {%0,%1,%2,%3};" \
                 : "+f"((c)[0]), "+f"((c)[1]), "+f"((c)[2]), "+f"((c)[3]) \
                 : "r"(a0), "r"(a1), "r"(a2), "r"(a3), "r"(b0), "r"(b1))

// fp32 pair -> bf16x2 hi (truncation) + bf16x2 lo (residual)
static __device__ __forceinline__ void cvt_pair(float2 f, uint32_t& hi, uint32_t& lo) {
    uint32_t u0 = __float_as_uint(f.x), u1 = __float_as_uint(f.y);
    hi = __byte_perm(u0, u1, 0x7632);
    float l0 = f.x - __uint_as_float(u0 & 0xffff0000u);
    float l1 = f.y - __uint_as_float(u1 & 0xffff0000u);
    asm("cvt.rn.bf16x2.f32 %0, %1, %2;" : "=r"(lo) : "f"(l1), "f"(l0));
}

// split float4 (4 consecutive k, 8B after split) and store hi/lo
static __device__ __forceinline__ void split_store(float4 v, uint32_t ahi, uint32_t alo) {
    uint32_t hi01, lo01, hi23, lo23;
    cvt_pair(make_float2(v.x, v.y), hi01, lo01);
    cvt_pair(make_float2(v.z, v.w), hi23, lo23);
    asm volatile("st.shared.v2.b32 [%0], {%1,%2};" :: "r"(ahi), "r"(hi01), "r"(hi23) : "memory");
    asm volatile("st.shared.v2.b32 [%0], {%1,%2};" :: "r"(alo), "r"(lo01), "r"(lo23) : "memory");
}

// ---- prep: blocks 0-63 build B fragment table; blocks 64-79 coeff tables ----
__global__ void rbf_prep(const float* __restrict__ in_b,
                         const float* __restrict__ centers,
                         const float* __restrict__ log_widths,
                         const float* __restrict__ out_weight,
                         const float* __restrict__ in_w)
{
    const int bid = blockIdx.x;
    const int tid = threadIdx.x;

    if (bid < 64) {
        int t = bid * 256 + tid;          // 0..16383
        int ks   = t >> 8;
        int nt8  = (t >> 5) & 7;
        int lane = t & 31;
        int n  = nt8 * 8 + (lane >> 2);
        int kk = ks * 16 + 2 * (lane & 3);
        const float* wr = in_w + n * DIMC + kk;
        uint32_t bh0, bl0, bh1, bl1;
        cvt_pair(make_float2(wr[0], wr[1]), bh0, bl0);
        cvt_pair(make_float2(wr[8], wr[9]), bh1, bl1);
        *(uint4*)(g_bf + (size_t)(ks * 8 + nt8) * 512 + lane * 16) =
            make_uint4(bh0, bh1, bl0, bl1);
        return;
    }

    const int i = (bid - 64) * 256 + tid;   // 0..4095
    const int h = i >> 6;
    const int k = i & 63;

    float lw = log_widths[i];
    float sp = (lw > 15.f) ? lw : log1pf(expf(lw));
    float w = sp + 0.001f;
    float s = -1.4426950408889634f / (w * w);
    float c = centers[i] - in_b[h];
    float4 q;
    q.x = s; q.y = -2.f * s * c; q.z = s * c * c; q.w = out_weight[i];
    g_q[i] = q;
    g_owt[i] = out_weight[((i & 63) << 6) + (i >> 6)];

    float c0  = centers[h * NB];
    float d   = (centers[h * NB + NB - 1] - c0) / (float)(NB - 1);
    float lw0 = log_widths[h * NB];
    bool ok = (fabsf(centers[i] - fmaf((float)k, d, c0)) <= 1e-5f) &&
              (fabsf(lw - lw0) <= 1e-6f);
    if (!ok) atomicAdd(&g_bad, 1);

    if (k == 0) {
        float sp0 = (lw0 > 15.f) ? lw0 : log1pf(expf(lw0));
        float w0  = sp0 + 0.001f;
        float sq  = -1.4426950408889634f / (w0 * w0);
        float A   = -2.f * sq * d;
        float B   = sq * d * d;
        float4 p1, p2;
        p1.x = c0 - in_b[h]; p1.y = sq; p1.z = d; p1.w = A;
        p2.x = B; p2.y = 2.f * B; p2.z = exp2f(2.f * B); p2.w = 0.f;
        g_p1[h] = p1; g_p2[h] = p2;
    }
}

// ---- fused GEMM + RBF: k32 double-buffered, 3 CTAs/SM ----
__global__ void __launch_bounds__(NT1, 3)
rbf_fused_kernel(const float* __restrict__ x,
                 const float* __restrict__ out_bias,
                 float* __restrict__ out)
{
    extern __shared__ char smem[];
    const uint32_t sb = smem_u32(smem);
    const int tid = threadIdx.x;
    const int wid = tid >> 5;
    const int l   = tid & 31;
    const int wq  = wid & 3;              // token quarter (32 tok)
    const int wh  = wid >> 2;             // h half (32 h)
    const int tok0 = blockIdx.x * MTILE;

    float acc[2][4][4];
#pragma unroll
    for (int m = 0; m < 2; ++m)
#pragma unroll
        for (int nt = 0; nt < 4; ++nt)
#pragma unroll
            for (int j = 0; j < 4; ++j) acc[m][nt][j] = 0.f;

    // --- producer constants (A: 128 rows x 32 k, rows r0+32*it) ---
    const int r0 = tid >> 3;               // 0..31
    const int c4 = tid & 7;                // float4 k-col within k32
    // swizzled store offset within A region: row*64 + ((c ^ ((row>>1)&3))<<4) + (c4&1)*8
    const uint32_t akey = (uint32_t)((r0 >> 1) & 3);
    const uint32_t acol = ((((uint32_t)c4 >> 1) ^ akey) << 4) + (uint32_t)(c4 & 1) * 8u;
    const float4* xg = (const float4*)x;
    const long arow_idx = (long)(tok0 + r0) * 256 + c4;   // +32it rows => +8192 idx
    // B producer: 32B per thread
    const char* bsrc = (const char*)g_bf + (size_t)tid * 32;
    const uint32_t bdst = BOFF + (uint32_t)tid * 32;

    // --- consumer constants ---
    const uint32_t rowA = (uint32_t)(wq * 32 + (l & 15));
    const uint32_t chA  = (uint32_t)(l >> 4);
    const uint32_t key2 = ((uint32_t)(l & 15) >> 1) & 3u;
    const uint32_t aoff = rowA * 64u;
    const uint32_t boff = BOFF + (uint32_t)(wh * 4) * 512u + (uint32_t)l * 16u;

    float4 pa[4];

    // ---- prologue: chunk 0 into stage 0 ----
#pragma unroll
    for (int it = 0; it < 4; ++it)
        pa[it] = xg[arow_idx + it * 8192];
#pragma unroll
    for (int it = 0; it < 4; ++it) {
        uint32_t ad = (uint32_t)(r0 + 32 * it) * 64u + acol;
        split_store(pa[it], sb + AHI + ad, sb + ALO + ad);
    }
    CP_ASYNC16(sb + bdst, bsrc);
    CP_ASYNC16(sb + bdst + 16, bsrc + 16);
    CP_COMMIT();
    CP_WAIT0();
    __syncthreads();

#pragma unroll 1
    for (int i = 0; i < 32; ++i) {
        const uint32_t sbase = sb + (uint32_t)(i & 1) * STAGE;
        const uint32_t dbase = sb + (uint32_t)((i + 1) & 1) * STAGE;

        if (i < 31) {
#pragma unroll
            for (int it = 0; it < 4; ++it)
                pa[it] = xg[arow_idx + (i + 1) * 8 + it * 8192];
            CP_ASYNC16(dbase + bdst, bsrc + (size_t)(i + 1) * 8192);
            CP_ASYNC16(dbase + bdst + 16, bsrc + (size_t)(i + 1) * 8192 + 16);
            CP_COMMIT();
        }

#pragma unroll
        for (int s2 = 0; s2 < 2; ++s2) {
            const uint32_t colA = (((uint32_t)(s2 * 2) + chA) ^ key2) << 4;
            uint32_t ah[2][4], al[2][4];
#pragma unroll
            for (int m = 0; m < 2; ++m) {
                uint32_t ra = sbase + aoff + (uint32_t)m * 1024u + colA;
                LDSM4(ah[m][0], ah[m][1], ah[m][2], ah[m][3], ra + AHI);
                LDSM4(al[m][0], al[m][1], al[m][2], al[m][3], ra + ALO);
            }
#pragma unroll
            for (int nt = 0; nt < 4; ++nt) {
                uint4 b;
                LDS128U(b, sbase + boff + (uint32_t)(s2 * 4096) + (uint32_t)nt * 512u);
#pragma unroll
                for (int m = 0; m < 2; ++m) {
                    MMA(acc[m][nt], ah[m][0], ah[m][1], ah[m][2], ah[m][3], b.x, b.y);
                    MMA(acc[m][nt], ah[m][0], ah[m][1], ah[m][2], ah[m][3], b.z, b.w);
                    MMA(acc[m][nt], al[m][0], al[m][1], al[m][2], al[m][3], b.x, b.y);
                }
            }
            if (s2 == 1 && i < 31) {
#pragma unroll
                for (int it = 0; it < 4; ++it) {
                    uint32_t ad = (uint32_t)(r0 + 32 * it) * 64u + acol;
                    split_store(pa[it], dbase + AHI + ad, dbase + ALO + ad);
                }
            }
        }
        if (i < 31) CP_WAIT0();
        __syncthreads();
    }

    // ---- overlay: z -> smem [128][66], stage tables ----
    {
        float* zs = (float*)(smem + OFF_ZS);
        const int g = l >> 2, t = l & 3;
#pragma unroll
        for (int m = 0; m < 2; ++m)
#pragma unroll
            for (int nt = 0; nt < 4; ++nt) {
                int tok = wq * 32 + m * 16 + g;
                int hcol = wh * 32 + nt * 8 + 2 * t;
                *(float2*)(zs + tok * 66 + hcol)       = make_float2(acc[m][nt][0], acc[m][nt][1]);
                *(float2*)(zs + (tok + 8) * 66 + hcol) = make_float2(acc[m][nt][2], acc[m][nt][3]);
            }
        float4* owt = (float4*)(smem + OFF_OWT);
        const float4* gow = (const float4*)g_owt;
#pragma unroll
        for (int j = 0; j < 4; ++j) owt[j * NT1 + tid] = gow[j * NT1 + tid];
        if (tid < NH) {
            ((float4*)(smem + OFF_P1))[tid] = g_p1[tid];
            ((float4*)(smem + OFF_P2))[tid] = g_p2[tid];
        }
    }
    __syncthreads();

    // ---- epilogue: thread = 4 tokens x 8 h ----
    const int hq = tid & 7;
    const int p  = tid >> 3;
    const float* zs = (const float*)(smem + OFF_ZS);
    const float4* p1s = (const float4*)(smem + OFF_P1);
    const float4* p2s = (const float4*)(smem + OFF_P2);
    float sum[4];

    if (g_bad == 0) {
        unsigned long long acc2[4] = {0ull, 0ull, 0ull, 0ull};
#pragma unroll
        for (int hp = 0; hp < 4; ++hp) {
            const int h0 = hq * 8 + 2 * hp;
            float4 Pa = p1s[h0], Pb = p1s[h0 + 1];
            float4 Qa = p2s[h0], Qb = p2s[h0 + 1];
            unsigned long long tt;
            PACK2(tt, Qa.z, Qb.z);
            float u0[4], u1[4], rb0[4], rb1[4];
#pragma unroll
            for (int j = 0; j < 4; ++j) {
                float2 zz = *(const float2*)(zs + (p + 32 * j) * 66 + h0);
                u0[j] = zz.x - Pa.x;  u1[j] = zz.y - Pb.x;
                rb0[j] = fmaf(Pa.w, u0[j], Qa.x);
                rb1[j] = fmaf(Pb.w, u1[j], Qb.x);
            }
            const uint32_t owbase = sb + OFF_OWT + (uint32_t)h0 * 4u;
#pragma unroll
            for (int m = 0; m < 4; ++m) {
                const float km = (float)(16 * m);
                unsigned long long e[4], r[4];
#pragma unroll
                for (int j = 0; j < 4; ++j) {
                    float v0 = fmaf(-km, Pa.z, u0[j]);
                    float v1 = fmaf(-km, Pb.z, u1[j]);
                    float e0, e1, rr0, rr1;
                    float a0 = Pa.y * v0 * v0, a1 = Pb.y * v1 * v1;
                    asm("ex2.approx.f32 %0, %1;" : "=f"(e0) : "f"(a0));
                    asm("ex2.approx.f32 %0, %1;" : "=f"(e1) : "f"(a1));
                    float b0 = fmaf(km, Qa.y, rb0[j]), b1 = fmaf(km, Qb.y, rb1[j]);
                    asm("ex2.approx.f32 %0, %1;" : "=f"(rr0) : "f"(b0));
                    asm("ex2.approx.f32 %0, %1;" : "=f"(rr1) : "f"(b1));
                    PACK2(e[j], e0, e1);
                    PACK2(r[j], rr0, rr1);
                }
                uint32_t a = owbase + (uint32_t)m * (16u * 256u);
#pragma unroll
                for (int kk = 0; kk < 16; ++kk) {
                    unsigned long long w2;
                    asm volatile("ld.shared.b64 %0, [%1];" : "=l"(w2) : "r"(a));
                    a += 256u;
#pragma unroll
                    for (int j = 0; j < 4; ++j) {
                        FMA2(acc2[j], e[j], w2);
                        MUL2(e[j], e[j], r[j]);
                        MUL2(r[j], r[j], tt);
                    }
                }
            }
        }
#pragma unroll
        for (int j = 0; j < 4; ++j) {
            float lo, hi;
            asm("mov.b64 {%0,%1}, %2;" : "=f"(lo), "=f"(hi) : "l"(acc2[j]));
            sum[j] = lo + hi;
        }
    } else {
#pragma unroll
        for (int j = 0; j < 4; ++j) sum[j] = 0.f;
#pragma unroll 1
        for (int i = 0; i < 8; ++i) {
            const int h = hq * 8 + i;
            const float4* qh = g_q + h * NB;
            float zh[4];
#pragma unroll
            for (int j = 0; j < 4; ++j) zh[j] = zs[(p + 32 * j) * 66 + h];
#pragma unroll 8
            for (int k = 0; k < NB; ++k) {
                float4 q = qh[k];
#pragma unroll
                for (int j = 0; j < 4; ++j) {
                    float pp = fmaf(fmaf(q.x, zh[j], q.y), zh[j], q.z);
                    float e;
                    asm("ex2.approx.f32 %0, %1;" : "=f"(e) : "f"(pp));
                    sum[j] = fmaf(e, q.w, sum[j]);
                }
            }
        }
    }

    const float ob = __ldg(out_bias);
#pragma unroll
    for (int j = 0; j < 4; ++j) {
        float v = sum[j];
        v += __shfl_xor_sync(0xffffffffu, v, 1);
        v += __shfl_xor_sync(0xffffffffu, v, 2);
        v += __shfl_xor_sync(0xffffffffu, v, 4);
        if (hq == 0) out[tok0 + p + 32 * j] = v + ob;
    }
}

extern "C" void kernel_launch(void* const* d_in, const int* in_sizes, int n_in,
                              void* d_out, int out_size)
{
    const float* x          = (const float*)d_in[0];
    const float* in_w       = (const float*)d_in[1];
    const float* in_b       = (const float*)d_in[2];
    const float* centers    = (const float*)d_in[3];
    const float* log_widths = (const float*)d_in[4];
    const float* out_weight = (const float*)d_in[5];
    const float* out_bias   = (const float*)d_in[6];
    float* out = (float*)d_out;

    int ntok = in_sizes[0] / DIMC;          // 65536

    rbf_prep<<<80, 256>>>(in_b, centers, log_widths, out_weight, in_w);

    cudaFuncSetAttribute(rbf_fused_kernel,
                         cudaFuncAttributeMaxDynamicSharedMemorySize, SMEM_TOTAL);
    rbf_fused_kernel<<<ntok / MTILE, NT1, SMEM_TOTAL>>>(x, out_bias, out);
}